// round 2
// baseline (speedup 1.0000x reference)
#include <cuda_runtime.h>
#include <math.h>
#include <float.h>

#define BB 16
#define NN 4096
#define CC 512
#define SS 8
#define HH 8
#define HD 64

// Scratch (allocation-free rule: __device__ globals)
__device__ float g_SA[BB*NN*SS];        // space_attn, natural (B,N,S) layout; flat view = SA2[b,s,n]
__device__ float g_P[BB*NN*SS];         // softmax(sa) over n, same flat layout
__device__ float g_tokens[BB*SS*CC];    // (B,S,C)
__device__ float g_qkv[BB*SS*3*CC];     // (B,S,3C)
__device__ float g_asp[BB*SS*CC];       // asp2 (B,S,C)

// ---------------------------------------------------------------------------
// K1: space_attn[b,n,s] = x[b,n,:] . w_sum[s,:] + b_sum[s]
// warp per (b,n) row; w_sum staged in smem; float4 coalesced x loads
// ---------------------------------------------------------------------------
__global__ void __launch_bounds__(256) k1_sa(const float* __restrict__ x,
                                             const float* __restrict__ w_sum,
                                             const float* __restrict__ b_sum) {
  __shared__ float4 wsm[SS][CC/4];
  __shared__ float bsm[SS];
  int tid = threadIdx.x;
  const float4* w4 = (const float4*)w_sum;
  for (int i = tid; i < SS*CC/4; i += 256) wsm[i >> 7][i & 127] = w4[i];
  if (tid < SS) bsm[tid] = b_sum[tid];
  __syncthreads();
  int warp = tid >> 5, lane = tid & 31;
  int g = blockIdx.x * 8 + warp;              // row index over B*N
  const float4* xr = (const float4*)(x + (size_t)g * CC);
  float acc[8] = {0,0,0,0,0,0,0,0};
#pragma unroll
  for (int k = 0; k < 4; k++) {
    float4 xv = xr[lane + 32*k];
#pragma unroll
    for (int s = 0; s < 8; s++) {
      float4 wv = wsm[s][lane + 32*k];
      acc[s] += xv.x*wv.x + xv.y*wv.y + xv.z*wv.z + xv.w*wv.w;
    }
  }
#pragma unroll
  for (int s = 0; s < 8; s++)
#pragma unroll
    for (int o = 16; o > 0; o >>= 1)
      acc[s] += __shfl_xor_sync(0xffffffffu, acc[s], o);
  if (lane == 0) {
    float* dst = g_SA + (size_t)g * SS;
#pragma unroll
    for (int s = 0; s < 8; s++) dst[s] = acc[s] + bsm[s];
  }
}

// ---------------------------------------------------------------------------
// K2: per-(b,s) softmax over the CONTIGUOUS 4096-float flat slab of g_SA
// ---------------------------------------------------------------------------
__global__ void __launch_bounds__(256) k2_softmax() {
  int b = blockIdx.x >> 3, s = blockIdx.x & 7;
  const float* base = g_SA + (size_t)b*NN*SS + (size_t)s*NN;
  float* pout      = g_P  + (size_t)b*NN*SS + (size_t)s*NN;
  __shared__ float sm[NN];
  __shared__ float red[8];
  __shared__ float red2[8];
  int tid = threadIdx.x, warp = tid>>5, lane = tid&31;
  float4* sm4 = (float4*)sm;
  const float4* b4 = (const float4*)base;
  for (int i = tid; i < NN/4; i += 256) sm4[i] = b4[i];
  __syncthreads();
  float m = -FLT_MAX;
  for (int i = tid; i < NN; i += 256) m = fmaxf(m, sm[i]);
#pragma unroll
  for (int o = 16; o; o >>= 1) m = fmaxf(m, __shfl_xor_sync(0xffffffffu, m, o));
  if (lane == 0) red[warp] = m;
  __syncthreads();
  m = red[0];
#pragma unroll
  for (int w = 1; w < 8; w++) m = fmaxf(m, red[w]);
  float z = 0.f;
  for (int i = tid; i < NN; i += 256) {
    float e = expf(sm[i] - m);
    sm[i] = e;
    z += e;
  }
#pragma unroll
  for (int o = 16; o; o >>= 1) z += __shfl_xor_sync(0xffffffffu, z, o);
  if (lane == 0) red2[warp] = z;
  __syncthreads();
  z = red2[0];
#pragma unroll
  for (int w = 1; w < 8; w++) z += red2[w];
  float iz = 1.f / z;
  float4* p4 = (float4*)pout;
  for (int i = tid; i < NN/4; i += 256) {
    float4 v = sm4[i];
    v.x *= iz; v.y *= iz; v.z *= iz; v.w *= iz;
    p4[i] = v;
  }
}

// ---------------------------------------------------------------------------
// K3: tokens[b,s,c] = max_n P2[b,s,n] * X2[b,c,n]
// block = (b, 4-wide c tile); threads stride n; 8x4 max accumulators in regs
// ---------------------------------------------------------------------------
__global__ void __launch_bounds__(256) k3_tokens(const float* __restrict__ x) {
  int b  = blockIdx.x >> 7;
  int c0 = (blockIdx.x & 127) << 2;
  const float* Pb = g_P + (size_t)b*NN*SS;
  const float* Xb = x   + (size_t)b*NN*CC;     // flat: X2[c][n] = Xb[c*NN + n]
  float mx[8][4];
#pragma unroll
  for (int s = 0; s < 8; s++)
#pragma unroll
    for (int j = 0; j < 4; j++) mx[s][j] = -FLT_MAX;
  for (int n = threadIdx.x; n < NN; n += 256) {
    float p[8], xv[4];
#pragma unroll
    for (int s = 0; s < 8; s++) p[s] = Pb[s*NN + n];
#pragma unroll
    for (int j = 0; j < 4; j++) xv[j] = Xb[(size_t)(c0+j)*NN + n];
#pragma unroll
    for (int s = 0; s < 8; s++)
#pragma unroll
      for (int j = 0; j < 4; j++) mx[s][j] = fmaxf(mx[s][j], p[s]*xv[j]);
  }
#pragma unroll
  for (int s = 0; s < 8; s++)
#pragma unroll
    for (int j = 0; j < 4; j++)
#pragma unroll
      for (int o = 16; o; o >>= 1)
        mx[s][j] = fmaxf(mx[s][j], __shfl_xor_sync(0xffffffffu, mx[s][j], o));
  __shared__ float red[8][32];
  int warp = threadIdx.x >> 5, lane = threadIdx.x & 31;
  if (lane == 0) {
#pragma unroll
    for (int s = 0; s < 8; s++)
#pragma unroll
      for (int j = 0; j < 4; j++) red[warp][s*4+j] = mx[s][j];
  }
  __syncthreads();
  if (threadIdx.x < 32) {
    float v = red[0][threadIdx.x];
#pragma unroll
    for (int w = 1; w < 8; w++) v = fmaxf(v, red[w][threadIdx.x]);
    int s = threadIdx.x >> 2, j = threadIdx.x & 3;
    g_tokens[(size_t)b*SS*CC + (size_t)s*CC + c0 + j] = v;
  }
}

// ---------------------------------------------------------------------------
// K4a: qkv[b,s,j] = tokens[b,s,:] . w_qkv[j,:]   (j in [0,1536))
// block = (b, 64-wide j tile), warp per 8 j's, tokens in smem
// ---------------------------------------------------------------------------
__global__ void __launch_bounds__(256) k4a_qkv(const float* __restrict__ w_qkv) {
  __shared__ float4 tok[SS][CC/4];
  int b = blockIdx.x;
  int j0 = blockIdx.y * 64;
  int tid = threadIdx.x;
  const float4* t4 = (const float4*)(g_tokens + (size_t)b*SS*CC);
  for (int i = tid; i < SS*CC/4; i += 256) tok[i>>7][i&127] = t4[i];
  __syncthreads();
  int warp = tid>>5, lane = tid&31;
#pragma unroll 1
  for (int jj = 0; jj < 8; jj++) {
    int j = j0 + warp*8 + jj;
    const float4* wr = (const float4*)(w_qkv + (size_t)j*CC);
    float acc[8] = {0,0,0,0,0,0,0,0};
#pragma unroll
    for (int k = 0; k < 4; k++) {
      float4 wv = wr[lane + 32*k];
#pragma unroll
      for (int s = 0; s < 8; s++) {
        float4 tv = tok[s][lane + 32*k];
        acc[s] += wv.x*tv.x + wv.y*tv.y + wv.z*tv.z + wv.w*tv.w;
      }
    }
#pragma unroll
    for (int s = 0; s < 8; s++)
#pragma unroll
      for (int o = 16; o; o >>= 1)
        acc[s] += __shfl_xor_sync(0xffffffffu, acc[s], o);
    if (lane == 0) {
#pragma unroll
      for (int s = 0; s < 8; s++)
        g_qkv[(size_t)b*SS*3*CC + (size_t)s*3*CC + j] = acc[s];
    }
  }
}

// ---------------------------------------------------------------------------
// K4b: per-(b,h) S=8 attention + w_cross mix, all in smem
// ---------------------------------------------------------------------------
__global__ void __launch_bounds__(256) k4b_attn(const float* __restrict__ w_cross) {
  int b = blockIdx.x >> 3, h = blockIdx.x & 7;
  __shared__ float q[8][64], kk[8][64], v[8][64], p[8][8], am[8][64];
  int tid = threadIdx.x;
  const float* src = g_qkv + (size_t)b*SS*3*CC;
  for (int i = tid; i < 512; i += 256) {
    int s = i >> 6, d = i & 63;
    q[s][d]  = src[s*1536 +        h*64 + d];
    kk[s][d] = src[s*1536 +  512 + h*64 + d];
    v[s][d]  = src[s*1536 + 1024 + h*64 + d];
  }
  __syncthreads();
  if (tid < 64) {
    int i = tid >> 3, j = tid & 7;
    float sc = 0.f;
#pragma unroll
    for (int d = 0; d < 64; d++) sc += q[i][d]*kk[j][d];
    p[i][j] = sc * 0.125f;           // hd^-0.5 = 1/8
  }
  __syncthreads();
  if (tid < 8) {
    int i = tid;
    float m = p[i][0];
#pragma unroll
    for (int j = 1; j < 8; j++) m = fmaxf(m, p[i][j]);
    float z = 0.f;
#pragma unroll
    for (int j = 0; j < 8; j++) { float e = expf(p[i][j]-m); p[i][j] = e; z += e; }
    float iz = 1.f/z;
#pragma unroll
    for (int j = 0; j < 8; j++) p[i][j] *= iz;
  }
  __syncthreads();
  for (int i2 = tid; i2 < 512; i2 += 256) {
    int i = i2 >> 6, d = i2 & 63;
    float a = 0.f;
#pragma unroll
    for (int j = 0; j < 8; j++) a += p[i][j]*v[j][d];
    am[i][d] = a;
  }
  __syncthreads();
  for (int i2 = tid; i2 < 512; i2 += 256) {
    int s = i2 >> 6, d = i2 & 63;
    float a = 0.f;
#pragma unroll
    for (int sp = 0; sp < 8; sp++) a += w_cross[s*8+sp]*am[sp][d];
    g_asp[(size_t)b*SS*CC + (size_t)s*CC + h*64 + d] = a;
  }
}

// ---------------------------------------------------------------------------
// K5: out[b,n,c] = LN_c( sum_s SA2[b,s,n]*asp2[b,s,c] )*gamma + beta + x[b,n,c]
// block covers 32 n rows of one batch; warp processes 2 n at a time (shares
// asp smem reads); asp2/gamma/beta in smem
// ---------------------------------------------------------------------------
__global__ void __launch_bounds__(256) k5_out(const float* __restrict__ x,
                                              const float* __restrict__ gamma,
                                              const float* __restrict__ beta,
                                              float* __restrict__ out) {
  __shared__ float4 aspm[SS][CC/4];
  __shared__ float4 gsm[CC/4], bsm[CC/4];
  int b  = blockIdx.x >> 7;
  int n0 = (blockIdx.x & 127) << 5;
  int tid = threadIdx.x;
  const float4* a4 = (const float4*)(g_asp + (size_t)b*SS*CC);
  for (int i = tid; i < SS*CC/4; i += 256) aspm[i>>7][i&127] = a4[i];
  if (tid < 128) {
    gsm[tid] = ((const float4*)gamma)[tid];
    bsm[tid] = ((const float4*)beta)[tid];
  }
  __syncthreads();
  int warp = tid>>5, lane = tid&31;
  const float* SAb = g_SA + (size_t)b*NN*SS;
#pragma unroll 1
  for (int pr = 0; pr < 2; pr++) {
    int n = n0 + warp*4 + pr*2;
    float w0[8], w1[8];
#pragma unroll
    for (int s = 0; s < 8; s++) {
      w0[s] = SAb[s*NN + n];
      w1[s] = SAb[s*NN + n + 1];
    }
    float4 t0[4], t1[4];
#pragma unroll
    for (int k = 0; k < 4; k++) {
      t0[k] = make_float4(0.f,0.f,0.f,0.f);
      t1[k] = make_float4(0.f,0.f,0.f,0.f);
    }
#pragma unroll
    for (int k = 0; k < 4; k++)
#pragma unroll
      for (int s = 0; s < 8; s++) {
        float4 a = aspm[s][lane + 32*k];
        t0[k].x += w0[s]*a.x; t0[k].y += w0[s]*a.y;
        t0[k].z += w0[s]*a.z; t0[k].w += w0[s]*a.w;
        t1[k].x += w1[s]*a.x; t1[k].y += w1[s]*a.y;
        t1[k].z += w1[s]*a.z; t1[k].w += w1[s]*a.w;
      }
    float s10=0.f, s20=0.f, s11=0.f, s21=0.f;
#pragma unroll
    for (int k = 0; k < 4; k++) {
      s10 += t0[k].x + t0[k].y + t0[k].z + t0[k].w;
      s20 += t0[k].x*t0[k].x + t0[k].y*t0[k].y + t0[k].z*t0[k].z + t0[k].w*t0[k].w;
      s11 += t1[k].x + t1[k].y + t1[k].z + t1[k].w;
      s21 += t1[k].x*t1[k].x + t1[k].y*t1[k].y + t1[k].z*t1[k].z + t1[k].w*t1[k].w;
    }
#pragma unroll
    for (int o = 16; o; o >>= 1) {
      s10 += __shfl_xor_sync(0xffffffffu, s10, o);
      s20 += __shfl_xor_sync(0xffffffffu, s20, o);
      s11 += __shfl_xor_sync(0xffffffffu, s11, o);
      s21 += __shfl_xor_sync(0xffffffffu, s21, o);
    }
    float mu0 = s10 * (1.f/CC);
    float r0  = rsqrtf(s20*(1.f/CC) - mu0*mu0 + 1e-5f);
    float mu1 = s11 * (1.f/CC);
    float r1  = rsqrtf(s21*(1.f/CC) - mu1*mu1 + 1e-5f);
    const float4* x0 = (const float4*)(x   + ((size_t)b*NN + n)*CC);
    const float4* x1 = x0 + CC/4;
    float4*       o0 = (float4*)(out + ((size_t)b*NN + n)*CC);
    float4*       o1 = o0 + CC/4;
#pragma unroll
    for (int k = 0; k < 4; k++) {
      int c4 = lane + 32*k;
      float4 g = gsm[c4], bb = bsm[c4];
      float4 xv = x0[c4];
      float4 ov;
      ov.x = (t0[k].x-mu0)*r0*g.x + bb.x + xv.x;
      ov.y = (t0[k].y-mu0)*r0*g.y + bb.y + xv.y;
      ov.z = (t0[k].z-mu0)*r0*g.z + bb.z + xv.z;
      ov.w = (t0[k].w-mu0)*r0*g.w + bb.w + xv.w;
      o0[c4] = ov;
      xv = x1[c4];
      ov.x = (t1[k].x-mu1)*r1*g.x + bb.x + xv.x;
      ov.y = (t1[k].y-mu1)*r1*g.y + bb.y + xv.y;
      ov.z = (t1[k].z-mu1)*r1*g.z + bb.z + xv.z;
      ov.w = (t1[k].w-mu1)*r1*g.w + bb.w + xv.w;
      o1[c4] = ov;
    }
  }
}

// ---------------------------------------------------------------------------

extern "C" void kernel_launch(void* const* d_in, const int* in_sizes, int n_in,
                              void* d_out, int out_size) {
  const float* x       = (const float*)d_in[0];
  const float* w_sum   = (const float*)d_in[1];
  const float* b_sum   = (const float*)d_in[2];
  const float* w_qkv   = (const float*)d_in[3];
  const float* w_cross = (const float*)d_in[4];
  const float* gamma   = (const float*)d_in[5];
  const float* beta    = (const float*)d_in[6];
  float* out = (float*)d_out;

  k1_sa<<<BB*NN/8, 256>>>(x, w_sum, b_sum);
  k2_softmax<<<BB*SS, 256>>>();
  k3_tokens<<<BB*(CC/4), 256>>>(x);
  k4a_qkv<<<dim3(BB, 3*CC/64), 256>>>(w_qkv);
  k4b_attn<<<BB*HH, 256>>>(w_cross);
  k5_out<<<BB*(NN/32), 256>>>(x, gamma, beta, out);
}